// round 15
// baseline (speedup 1.0000x reference)
#include <cuda_runtime.h>
#include <cstdint>

// ChamferDistance: B=4, N=8192, C=3 — uniform-grid NN, group-of-4 query.
// k_build: 8 blocks (one grid each): smem hist -> scan -> scatter.
// k_query: each query handled by a 4-lane GROUP (lanes split each cell's
// candidate list, share `best` after every cell via sub-group shfl).
// 4x occupancy + 4x less serial load latency vs one-thread-per-query.
//
// G=16 (h=0.5). Cell scanned only if its box lower bound beats best;
// boundary cells extend to infinity outward (clamped outliers). Ring stops
// when best <= (m + R*h)^2. Deterministic: mins are exact under candidate
// reordering; prune decisions depend only on exact mins; fixed-order sums.

constexpr int B_    = 4;
constexpr int N_    = 8192;
constexpr int NGRID = 8;                 // gid = b*2 + s (s=0: p1, s=1: p2)
constexpr int G     = 16;
constexpr int CELLS = G * G * G;         // 4096
constexpr float H    = 0.5f;
constexpr float ORG  = -4.0f;
constexpr float INVH = 2.0f;
constexpr int GRP   = 4;                 // lanes per query
constexpr int QBLK  = 1024;              // query blocks (256 thr each)

__device__ int2   g_rng[NGRID][CELLS];   // {start, count}
__device__ float4 g_pts[NGRID][N_];      // sorted points, .w = original index
__device__ float  g_part[QBLK];
__device__ unsigned int g_done = 0;

__device__ __forceinline__ int cellof(float v) {
    int i = (int)floorf((v - ORG) * INVH);
    return i < 0 ? 0 : (i > G - 1 ? G - 1 : i);
}

// ---- 1. fused build: one block per grid ------------------------------
__global__ __launch_bounds__(1024)
void k_build(const float* __restrict__ p1, const float* __restrict__ p2)
{
    __shared__ int cnt[CELLS];
    __shared__ int cur[CELLS];
    __shared__ int ssum[1024];

    const int gid = blockIdx.x;
    const int tid = threadIdx.x;
    const int b = gid >> 1, s = gid & 1;
    const float* __restrict__ src = (s ? p2 : p1) + (size_t)b * N_ * 3;

    #pragma unroll
    for (int k = 0; k < CELLS / 1024; k++) cnt[tid + k * 1024] = 0;
    __syncthreads();

    #pragma unroll
    for (int k = 0; k < N_ / 1024; k++) {
        const int i = tid + k * 1024;
        const float x = src[i * 3 + 0], y = src[i * 3 + 1], z = src[i * 3 + 2];
        const int c = (cellof(z) * G + cellof(y)) * G + cellof(x);
        atomicAdd(&cnt[c], 1);
    }
    __syncthreads();

    const int base = tid * 4;
    int sv = cnt[base] + cnt[base + 1] + cnt[base + 2] + cnt[base + 3];
    ssum[tid] = sv;
    __syncthreads();
    for (int off = 1; off < 1024; off <<= 1) {
        int v = (tid >= off) ? ssum[tid - off] : 0;
        __syncthreads();
        ssum[tid] += v;
        __syncthreads();
    }
    int run = ssum[tid] - sv;
    #pragma unroll
    for (int j = 0; j < 4; j++) {
        const int c = base + j;
        const int n = cnt[c];
        g_rng[gid][c] = make_int2(run, n);
        cur[c] = run;
        run += n;
    }
    __syncthreads();

    #pragma unroll
    for (int k = 0; k < N_ / 1024; k++) {
        const int i = tid + k * 1024;
        const float x = src[i * 3 + 0], y = src[i * 3 + 1], z = src[i * 3 + 2];
        const int c = (cellof(z) * G + cellof(y)) * G + cellof(x);
        const int pos = atomicAdd(&cur[c], 1);
        g_pts[gid][pos] = make_float4(x, y, z, __int_as_float(i));
    }
}

// lane-strided scan of one cell's point list (this lane takes sub, sub+4, ...)
__device__ __forceinline__ float scan_cell_g(const float4* __restrict__ pts,
                                             int2 rg, int sub,
                                             float qx, float qy, float qz,
                                             float best)
{
    const int e = rg.x + rg.y;
    for (int t = rg.x + sub; t < e; t += GRP) {
        const float4 A = pts[t];
        const float ax = qx - A.x, ay = qy - A.y, az = qz - A.z;
        float d = ax * ax; d = fmaf(ay, ay, d); d = fmaf(az, az, d);
        best = fminf(best, d);
    }
    return best;
}

// per-axis box distance; boundary cells extend to infinity outward
__device__ __forceinline__ float axdist(int c, float qv) {
    const float lo = ORG + c * H;
    const float dlo = (c == 0)     ? 0.0f : lo - qv;
    const float dhi = (c == G - 1) ? 0.0f : qv - lo - H;
    return fmaxf(fmaxf(dlo, dhi), 0.0f);
}

// ---- 2. group-of-4 pruned ring-search + fused deterministic sum ------
__global__ __launch_bounds__(256)
void k_query(float* __restrict__ out)
{
    const int tidg = blockIdx.x * 256 + threadIdx.x;   // 262144 threads
    const int qid  = tidg >> 2;                        // 65536 queries
    const int sub  = tidg & (GRP - 1);
    const int gid  = qid >> 13, i = qid & (N_ - 1);
    const int og   = gid ^ 1;
    const int tid  = threadIdx.x;

    // sub-group shuffle mask: the 4 lanes of this group
    const unsigned int gmask = 0xFu << ((threadIdx.x & 31) & ~(GRP - 1));

    const float4 qp = g_pts[gid][i];                   // sorted -> coherent
    const float qx = qp.x, qy = qp.y, qz = qp.z;
    const int cx = cellof(qx), cy = cellof(qy), cz = cellof(qz);

    const float lox = ORG + cx * H, loy = ORG + cy * H, loz = ORG + cz * H;
    float m = fminf(fminf(qx - lox, lox + H - qx),
             fminf(fminf(qy - loy, loy + H - qy),
                   fminf(qz - loz, loz + H - qz)));
    m = fmaxf(m, 0.0f);

    const int2*   __restrict__ rng = g_rng[og];
    const float4* __restrict__ pts = g_pts[og];

    float best = 1e30f;   // kept group-synchronized after every cell scan
    for (int R = 0; R < G; R++) {
        if (R == 0) {
            best = scan_cell_g(pts, rng[(cz * G + cy) * G + cx], sub,
                               qx, qy, qz, best);
            best = fminf(best, __shfl_xor_sync(gmask, best, 1));
            best = fminf(best, __shfl_xor_sync(gmask, best, 2));
        } else {
            for (int dz = -R; dz <= R; dz++) {
                const int z = cz + dz;
                if ((unsigned)z >= (unsigned)G) continue;
                const float dzb = axdist(z, qz);
                const float dz2 = dzb * dzb;
                if (dz2 >= best) continue;
                const bool zedge = (dz == -R) | (dz == R);
                for (int dy = -R; dy <= R; dy++) {
                    const int y = cy + dy;
                    if ((unsigned)y >= (unsigned)G) continue;
                    const float dyb = axdist(y, qy);
                    const float dzy2 = fmaf(dyb, dyb, dz2);
                    if (dzy2 >= best) continue;
                    const bool edge = zedge | (dy == -R) | (dy == R);
                    const int step = edge ? 1 : 2 * R;
                    for (int dx = -R; dx <= R; dx += step) {
                        const int x = cx + dx;
                        if ((unsigned)x >= (unsigned)G) continue;
                        const float dxb = axdist(x, qx);
                        const float lb2 = fmaf(dxb, dxb, dzy2);
                        if (lb2 >= best) continue;       // group-uniform prune
                        const int2 rg = rng[(z * G + y) * G + x];
                        if (rg.y == 0) continue;
                        best = scan_cell_g(pts, rg, sub, qx, qy, qz, best);
                        best = fminf(best, __shfl_xor_sync(gmask, best, 1));
                        best = fminf(best, __shfl_xor_sync(gmask, best, 2));
                    }
                }
            }
        }
        const float bound = m + (float)R * H;
        if (best <= bound * bound) break;
    }

    // ---- fused deterministic reduction (sub==0 contributes per query) ----
    __syncwarp();
    float sv = (sub == 0) ? best : 0.0f;
    #pragma unroll
    for (int o = 16; o > 0; o >>= 1)
        sv += __shfl_down_sync(0xffffffffu, sv, o);
    __shared__ float red[8];
    __shared__ bool  amLast;
    if ((tid & 31) == 0) red[tid >> 5] = sv;
    __syncthreads();
    if (tid == 0) {
        float bs = 0.0f;
        #pragma unroll
        for (int wi = 0; wi < 8; wi++) bs += red[wi];
        g_part[blockIdx.x] = bs;
        __threadfence();
        amLast = (atomicAdd(&g_done, 1u) == QBLK - 1);
    }
    __syncthreads();

    if (amLast) {
        float v = g_part[tid] + g_part[tid + 256]
                + g_part[tid + 512] + g_part[tid + 768];
        #pragma unroll
        for (int o = 16; o > 0; o >>= 1)
            v += __shfl_down_sync(0xffffffffu, v, o);
        if ((tid & 31) == 0) red[tid >> 5] = v;
        __syncthreads();
        if (tid == 0) {
            float t = 0.0f;
            #pragma unroll
            for (int wi = 0; wi < 8; wi++) t += red[wi];
            out[0] = t * (1.0f / (float)N_);
            g_done = 0;                   // reset for next graph replay
        }
    }
}

extern "C" void kernel_launch(void* const* d_in, const int* in_sizes, int n_in,
                              void* d_out, int out_size)
{
    const float* points1 = (const float*)d_in[0];
    const float* points2 = (const float*)d_in[1];
    float* out = (float*)d_out;

    k_build<<<NGRID, 1024>>>(points1, points2);
    k_query<<<QBLK, 256>>>(out);
}

// round 16
// speedup vs baseline: 1.5144x; 1.5144x over previous
#include <cuda_runtime.h>
#include <cstdint>

// ChamferDistance: B=4, N=8192, C=3
// loss = sum_b [ mean_i min_j d2 + mean_j min_i d2 ]
//
// R11 structure (best known) with ALL min accumulation moved to integer
// IMNMX.U32 on the alu pipe: fp pipe now carries only the 32 packed f32x2
// ops per p-iter (64 SMSP-cyc), alu 64, issue ~74 -> binder cut ~23% vs
// R11's 96. Integer compare == float compare for the strictly positive
// minima here; cancellation-negative d sorts as huge uint = clamped away
// (matches reference clamp semantics; R11 passed rel_err 0.0 this way).
// Row warp-reduce: redux.sync.min.u32; cross-block combine: atomicMax on
// complemented bits (exact, order-independent -> deterministic).

constexpr int B_      = 4;
constexpr int N_      = 8192;
constexpr int THREADS = 128;            // 4 warps
constexpr int RPT     = 8;              // refs (P2 points) per thread
constexpr int RPW     = 32 * RPT;       // 256 refs per warp
constexpr int RPB     = 4 * RPW;        // 1024 refs per block
constexpr int QPB     = 256;            // P1 queries per block (128 pairs)
constexpr int NQG     = N_ / QPB;       // 32 query groups
constexpr int NRG     = N_ / RPB;       // 8 ref groups
constexpr int NBLOCKS = B_ * NQG * NRG; // 1024
constexpr int NSLOT   = 2 * B_ * N_;    // 65536 min slots (rows then cols)
constexpr int CBLK    = 256;            // combine blocks

__device__ unsigned int g_min[NSLOT];   // 0 loses to any complemented value
__device__ float        g_part[CBLK];
__device__ unsigned int g_done = 0;

__device__ __forceinline__ uint64_t pack2(float lo, float hi) {
    uint64_t r;
    asm("mov.b64 %0, {%1, %2};" : "=l"(r) : "f"(lo), "f"(hi));
    return r;
}
__device__ __forceinline__ void unpack2u(uint64_t v, unsigned int& lo, unsigned int& hi) {
    asm("mov.b64 {%0, %1}, %2;" : "=r"(lo), "=r"(hi) : "l"(v));
}
__device__ __forceinline__ uint64_t fma2(uint64_t a, uint64_t b, uint64_t c) {
    uint64_t r;
    asm("fma.rn.f32x2 %0, %1, %2, %3;" : "=l"(r) : "l"(a), "l"(b), "l"(c));
    return r;
}
__device__ __forceinline__ uint64_t add2(uint64_t a, uint64_t b) {
    uint64_t r;
    asm("add.rn.f32x2 %0, %1, %2;" : "=l"(r) : "l"(a), "l"(b));
    return r;
}
__device__ __forceinline__ unsigned int redux_min(unsigned int v) {
    unsigned int r;
    asm("redux.sync.min.u32 %0, %1, 0xffffffff;" : "=r"(r) : "r"(v));
    return r;
}
__device__ __forceinline__ unsigned int umin2(unsigned int a, unsigned int b) {
    return a < b ? a : b;   // IMNMX.U32 (alu pipe)
}

__global__ __launch_bounds__(THREADS, 4)
void chamfer_main(const float* __restrict__ p1, const float* __restrict__ p2)
{
    const int blk = blockIdx.x;
    const int rg  = blk & (NRG - 1);          // 0..7
    const int qg  = (blk >> 3) & (NQG - 1);   // 0..31
    const int b   = blk >> 8;                 // 0..3

    const float* __restrict__ q = p1 + (size_t)b * N_ * 3;
    const float* __restrict__ r = p2 + (size_t)b * N_ * 3;

    // Query-pair tiles: sh_a[p]={qx0,qx1,qy0,qy1}, sh_b[p]={qz0,qz1,qs0,qs1}
    __shared__ float4 sh_a[QPB / 2];
    __shared__ float4 sh_b[QPB / 2];

    const int tid   = threadIdx.x;
    const int lane  = tid & 31;
    const int w     = tid >> 5;
    const int qbase = qg * QPB;

    // Stage 128 query pairs (one per thread)
    {
        const float2* qp = (const float2*)(q + (size_t)(qbase + 2 * tid) * 3);
        const float2 a = qp[0];   // x0 y0
        const float2 c = qp[1];   // z0 x1
        const float2 e = qp[2];   // y1 z1
        const float x0 = a.x, y0 = a.y, z0 = c.x;
        const float x1 = c.y, y1 = e.x, z1 = e.y;
        sh_a[tid] = make_float4(x0, x1, y0, y1);
        sh_b[tid] = make_float4(z0, z1,
                                x0 * x0 + y0 * y0 + z0 * z0,
                                x1 * x1 + y1 * y1 + z1 * z1);
    }

    // 8 private refs: -2r replicated-packed, |r|^2 replicated-packed
    uint64_t nrx[RPT], nry[RPT], nrz[RPT], pw2[RPT];
    unsigned int mcol[RPT];     // col-min accumulators, all integer (alu pipe)
    const int jbase = rg * RPB + w * RPW + lane;
    #pragma unroll
    for (int k = 0; k < RPT; k++) {
        const int j = jbase + k * 32;
        const float rx = r[j * 3 + 0], ry = r[j * 3 + 1], rz = r[j * 3 + 2];
        nrx[k] = pack2(-2.0f * rx, -2.0f * rx);
        nry[k] = pack2(-2.0f * ry, -2.0f * ry);
        nrz[k] = pack2(-2.0f * rz, -2.0f * rz);
        const float rw = rx * rx + ry * ry + rz * rz;
        pw2[k] = pack2(rw, rw);
        mcol[k] = 0xffffffffu;
    }

    __syncthreads();

    const ulonglong2* __restrict__ sa = (const ulonglong2*)sh_a;
    const ulonglong2* __restrict__ sb = (const ulonglong2*)sh_b;
    const int rowslot = b * N_ + qbase;

    #pragma unroll 4
    for (int p = 0; p < QPB / 2; p++) {
        const ulonglong2 va = sa[p];      // qx2, qy2 (packed query pair)
        const ulonglong2 vb = sb[p];      // qz2, qs2
        const uint64_t qx2 = va.x, qy2 = va.y;
        const uint64_t qz2 = vb.x, qs2 = vb.y;

        // integer row accumulators (split even/odd k to relax chains)
        unsigned int rla = 0xffffffffu, rlb = 0xffffffffu;
        unsigned int rha = 0xffffffffu, rhb = 0xffffffffu;

        #pragma unroll
        for (int k = 0; k < RPT; k += 2) {
            {
                uint64_t d = fma2(nrx[k], qx2, qs2);
                d = fma2(nry[k], qy2, d);
                d = fma2(nrz[k], qz2, d);
                d = add2(d, pw2[k]);
                unsigned int udl, udh; unpack2u(d, udl, udh);
                mcol[k] = umin2(mcol[k], umin2(udl, udh));
                rla = umin2(rla, udl);
                rha = umin2(rha, udh);
            }
            {
                uint64_t d = fma2(nrx[k + 1], qx2, qs2);
                d = fma2(nry[k + 1], qy2, d);
                d = fma2(nrz[k + 1], qz2, d);
                d = add2(d, pw2[k + 1]);
                unsigned int udl, udh; unpack2u(d, udl, udh);
                mcol[k + 1] = umin2(mcol[k + 1], umin2(udl, udh));
                rlb = umin2(rlb, udl);
                rhb = umin2(rhb, udh);
            }
        }

        // warp row-min: single integer redux on raw bits
        const unsigned int url = redux_min(umin2(rla, rlb));
        const unsigned int urh = redux_min(umin2(rha, rhb));
        if (lane == 0) {
            atomicMax(&g_min[rowslot + 2 * p],     ~url);
            atomicMax(&g_min[rowslot + 2 * p + 1], ~urh);
        }
    }

    // publish col-mins (exact bitwise min across the 32 query groups)
    const int colbase = B_ * N_ + b * N_;
    #pragma unroll
    for (int k = 0; k < RPT; k++)
        atomicMax(&g_min[colbase + jbase + k * 32], ~mcol[k]);
}

__global__ __launch_bounds__(256)
void chamfer_combine(float* __restrict__ out)
{
    const int tid = threadIdx.x;
    const int base = blockIdx.x * (NSLOT / CBLK);    // 256 slots per block
    float s = 0.0f;
    // one slot per thread: single load, no inner loop latency chain
    {
        const unsigned int u = g_min[base + tid];
        s = fmaxf(__uint_as_float(~u), 0.0f);        // clamp like the reference
        g_min[base + tid] = 0u;                      // reset for next replay
    }

    #pragma unroll
    for (int o = 16; o > 0; o >>= 1)
        s += __shfl_down_sync(0xffffffffu, s, o);
    __shared__ float red[8];
    __shared__ bool  amLast;
    if ((tid & 31) == 0) red[tid >> 5] = s;
    __syncthreads();
    if (tid == 0) {
        float bs = 0.0f;
        #pragma unroll
        for (int wi = 0; wi < 8; wi++) bs += red[wi];
        g_part[blockIdx.x] = bs;
        __threadfence();
        amLast = (atomicAdd(&g_done, 1u) == CBLK - 1);
    }
    __syncthreads();

    if (amLast) {
        float v = g_part[tid];            // 256 threads, 256 partials
        #pragma unroll
        for (int o = 16; o > 0; o >>= 1)
            v += __shfl_down_sync(0xffffffffu, v, o);
        if ((tid & 31) == 0) red[tid >> 5] = v;
        __syncthreads();
        if (tid == 0) {
            float t = 0.0f;
            #pragma unroll
            for (int wi = 0; wi < 8; wi++) t += red[wi];
            out[0] = t * (1.0f / (float)N_);
            g_done = 0;                   // reset for next graph replay
        }
    }
}

extern "C" void kernel_launch(void* const* d_in, const int* in_sizes, int n_in,
                              void* d_out, int out_size)
{
    const float* points1 = (const float*)d_in[0];
    const float* points2 = (const float*)d_in[1];
    float* out = (float*)d_out;

    chamfer_main<<<NBLOCKS, THREADS>>>(points1, points2);
    chamfer_combine<<<CBLK, 256>>>(out);
}